// round 1
// baseline (speedup 1.0000x reference)
#include <cuda_runtime.h>
#include <math.h>

// Problem constants (fixed shapes per reference)
#define N_NODES 30000
#define N_EDGES 480000
#define IN_F    128
#define NHEAD   4
#define HD      512        // NHEAD * 128
#define OUTF    128
#define NEG_SLOPE 0.2f
#define BN_EPS  1e-5f
#define BN_BLOCKS 256

// ---------------- scratch (static __device__, no allocations) ----------------
__device__ float g_h[N_NODES * HD];        // projected feats
__device__ float g_rst[N_NODES * HD];      // res+bias, then GAT output (BN input)
__device__ float g_el[N_NODES * NHEAD];
__device__ float g_er[N_NODES * NHEAD];
__device__ int   g_deg[N_NODES];
__device__ int   g_cursor[N_NODES];
__device__ int   g_ptr[N_NODES + 1];
__device__ int   g_srcs[N_EDGES];          // CSR (by dst) of source node ids
__device__ float g_psum[BN_BLOCKS * HD];
__device__ float g_psq[BN_BLOCKS * HD];
__device__ float g_scale[HD];
__device__ float g_shift[HD];

// ---------------- packed f32x2 helpers (sm_103a FFMA2) ----------------
__device__ __forceinline__ unsigned long long pack2(float x) {
    unsigned long long r;
    asm("mov.b64 %0, {%1, %1};" : "=l"(r) : "f"(x));
    return r;
}
__device__ __forceinline__ void fma2(unsigned long long& d, unsigned long long a,
                                     unsigned long long b) {
    asm("fma.rn.f32x2 %0, %1, %2, %3;" : "=l"(d) : "l"(a), "l"(b), "l"(d));
}
__device__ __forceinline__ float2 unpack2(unsigned long long v) {
    float lo, hi;
    asm("mov.b64 {%0, %1}, %2;" : "=f"(lo), "=f"(hi) : "l"(v));
    return make_float2(lo, hi);
}

// ---------------- kernel 0: zero degree histogram ----------------
__global__ void zero_deg_kernel() {
    int i = blockIdx.x * blockDim.x + threadIdx.x;
    if (i < N_NODES) g_deg[i] = 0;
}

// ---------------- kernel 1: GEMM1  h = feat@W_fc ; rst = feat@W_res + bias ----
// C[30000 x 1024] = feat[30000 x 128] @ [W_fc | W_res]
// BM=128 BN=128 BK=32, 256 threads, thread computes 8x8 via 8x4 f32x2 accs.
__global__ __launch_bounds__(256) void gemm1_kernel(
    const float* __restrict__ feat, const float* __restrict__ Wfc,
    const float* __restrict__ Wres, const float* __restrict__ bias) {
    __shared__ float As[32][129];   // k-major, padded
    __shared__ float Bs[32][128];
    const int tid = threadIdx.x;
    const int tx = tid & 15, ty = tid >> 4;
    const int row0 = blockIdx.y * 128;
    const int bx = blockIdx.x;   // 0..7 (8 col blocks of 128 over 1024)
    const float* B = (bx < 4) ? (Wfc + bx * 128) : (Wres + (bx - 4) * 128);

    unsigned long long acc[8][4];
#pragma unroll
    for (int i = 0; i < 8; i++)
#pragma unroll
        for (int p = 0; p < 4; p++) acc[i][p] = 0ULL;

    for (int kt = 0; kt < 128; kt += 32) {
        // load A tile 128x32 (transposed into k-major)
#pragma unroll
        for (int l = 0; l < 4; l++) {
            int e = (tid + l * 256) * 4;
            int r = e >> 5, k = e & 31;
            float4 v = make_float4(0.f, 0.f, 0.f, 0.f);
            int gr = row0 + r;
            if (gr < N_NODES) v = *(const float4*)(feat + gr * 128 + kt + k);
            As[k + 0][r] = v.x; As[k + 1][r] = v.y;
            As[k + 2][r] = v.z; As[k + 3][r] = v.w;
        }
        // load B tile 32x128
#pragma unroll
        for (int l = 0; l < 4; l++) {
            int e = (tid + l * 256) * 4;
            int k = e >> 7, c = e & 127;
            *(float4*)&Bs[k][c] = *(const float4*)(B + (kt + k) * 512 + c);
        }
        __syncthreads();
#pragma unroll
        for (int kk = 0; kk < 32; kk++) {
            unsigned long long a2[8], b2[4];
#pragma unroll
            for (int i = 0; i < 8; i++) a2[i] = pack2(As[kk][ty * 8 + i]);
#pragma unroll
            for (int p = 0; p < 4; p++)
                b2[p] = *(const unsigned long long*)&Bs[kk][tx * 8 + p * 2];
#pragma unroll
            for (int i = 0; i < 8; i++)
#pragma unroll
                for (int p = 0; p < 4; p++) fma2(acc[i][p], a2[i], b2[p]);
        }
        __syncthreads();
    }
    // epilogue: split into g_h (cols<512) / g_rst (+bias)
#pragma unroll
    for (int i = 0; i < 8; i++) {
        int gr = row0 + ty * 8 + i;
        if (gr >= N_NODES) continue;
#pragma unroll
        for (int p = 0; p < 4; p++) {
            float2 v = unpack2(acc[i][p]);
            int gc = bx * 128 + tx * 8 + p * 2;   // 0..1023
            if (gc < 512) {
                g_h[gr * HD + gc] = v.x;
                g_h[gr * HD + gc + 1] = v.y;
            } else {
                int c = gc - 512;
                g_rst[gr * HD + c] = v.x + bias[c];
                g_rst[gr * HD + c + 1] = v.y + bias[c + 1];
            }
        }
    }
}

// ---------------- kernel 2: el/er per (node, head) ----------------
__global__ void el_er_kernel(const float* __restrict__ attn_l,
                             const float* __restrict__ attn_r) {
    int w = (blockIdx.x * blockDim.x + threadIdx.x) >> 5;
    int lane = threadIdx.x & 31;
    if (w >= N_NODES) return;
#pragma unroll
    for (int hh = 0; hh < NHEAD; hh++) {
        float4 hv = *(const float4*)(g_h + w * HD + hh * 128 + lane * 4);
        float4 al = *(const float4*)(attn_l + hh * 128 + lane * 4);
        float4 ar = *(const float4*)(attn_r + hh * 128 + lane * 4);
        float dl = hv.x * al.x + hv.y * al.y + hv.z * al.z + hv.w * al.w;
        float dr = hv.x * ar.x + hv.y * ar.y + hv.z * ar.z + hv.w * ar.w;
#pragma unroll
        for (int o = 16; o; o >>= 1) {
            dl += __shfl_xor_sync(0xffffffffu, dl, o);
            dr += __shfl_xor_sync(0xffffffffu, dr, o);
        }
        if (lane == 0) {
            g_el[w * NHEAD + hh] = dl;
            g_er[w * NHEAD + hh] = dr;
        }
    }
}

// ---------------- kernel 3: degree histogram ----------------
__global__ void hist_kernel(const int* __restrict__ dst) {
    int e = blockIdx.x * blockDim.x + threadIdx.x;
    if (e < N_EDGES) atomicAdd(&g_deg[dst[e]], 1);
}

// ---------------- kernel 4: single-block scan -> csr_ptr, cursor --------------
__global__ void scan_kernel() {
    __shared__ int sh[1024];
    int t = threadIdx.x;
    int carry = 0;
    if (t == 0) g_ptr[0] = 0;
    for (int chunk = 0; chunk < 30; chunk++) {
        int idx = chunk * 1024 + t;
        int v = (idx < N_NODES) ? g_deg[idx] : 0;
        sh[t] = v;
        __syncthreads();
        for (int o = 1; o < 1024; o <<= 1) {
            int add = (t >= o) ? sh[t - o] : 0;
            __syncthreads();
            sh[t] += add;
            __syncthreads();
        }
        int incl = sh[t];
        if (idx < N_NODES) {
            g_ptr[idx + 1] = carry + incl;
            g_cursor[idx] = carry + incl - v;   // exclusive
        }
        carry += sh[1023];
        __syncthreads();
    }
}

// ---------------- kernel 5: scatter edges into CSR ----------------
__global__ void scatter_kernel(const int* __restrict__ src,
                               const int* __restrict__ dst) {
    int e = blockIdx.x * blockDim.x + threadIdx.x;
    if (e < N_EDGES) {
        int p = atomicAdd(&g_cursor[dst[e]], 1);
        g_srcs[p] = src[e];
    }
}

// ---------------- kernel 6: softmax + aggregate, warp per (node, head) --------
__global__ __launch_bounds__(256) void agg_kernel() {
    int gw = (blockIdx.x * 256 + threadIdx.x) >> 5;
    int lane = threadIdx.x & 31;
    if (gw >= N_NODES * NHEAD) return;
    int v = gw >> 2, hh = gw & 3;
    int start = g_ptr[v], end = g_ptr[v + 1];
    if (start == end) return;   // rst keeps residual+bias (matches reference)
    float er_v = g_er[v * NHEAD + hh];

    // pass 1: max of leaky(el[s]+er[v])
    float m = -1e30f;
    for (int j = start + lane; j < end; j += 32) {
        int s = g_srcs[j];
        float x = g_el[s * NHEAD + hh] + er_v;
        x = (x > 0.f) ? x : NEG_SLOPE * x;
        m = fmaxf(m, x);
    }
#pragma unroll
    for (int o = 16; o; o >>= 1) m = fmaxf(m, __shfl_xor_sync(0xffffffffu, m, o));

    // pass 2: weighted accumulate (each lane owns 4 dims, coalesced float4)
    float4 acc = make_float4(0.f, 0.f, 0.f, 0.f);
    float denom = 0.f;
    for (int j = start; j < end; j++) {
        int s = g_srcs[j];                       // broadcast load
        float x = g_el[s * NHEAD + hh] + er_v;   // broadcast load
        x = (x > 0.f) ? x : NEG_SLOPE * x;
        float w = expf(x - m);
        denom += w;
        float4 hv = *(const float4*)(g_h + s * HD + hh * 128 + lane * 4);
        acc.x += w * hv.x; acc.y += w * hv.y;
        acc.z += w * hv.z; acc.w += w * hv.w;
    }
    float inv = 1.0f / denom;
    float* o = g_rst + v * HD + hh * 128 + lane * 4;
    float4 cur = *(float4*)o;
    cur.x += acc.x * inv; cur.y += acc.y * inv;
    cur.z += acc.z * inv; cur.w += acc.w * inv;
    *(float4*)o = cur;
}

// ---------------- kernel 7: BN partial sums (deterministic) ----------------
__global__ void bn_part_kernel() {
    int c = threadIdx.x;   // 512
    float s = 0.f, q = 0.f;
    for (int r = blockIdx.x; r < N_NODES; r += gridDim.x) {
        float x = g_rst[r * HD + c];
        s += x;
        q += x * x;
    }
    g_psum[blockIdx.x * HD + c] = s;
    g_psq[blockIdx.x * HD + c] = q;
}

// ---------------- kernel 8: BN finalize -> scale/shift ----------------
__global__ void bn_final_kernel(const float* __restrict__ gamma,
                                const float* __restrict__ beta) {
    int c = threadIdx.x;
    float s = 0.f, q = 0.f;
    for (int b = 0; b < BN_BLOCKS; b++) {
        s += g_psum[b * HD + c];
        q += g_psq[b * HD + c];
    }
    float mu = s / (float)N_NODES;
    float var = q / (float)N_NODES - mu * mu;
    float rstd = rsqrtf(var + BN_EPS);
    float sc = gamma[c] * rstd;
    g_scale[c] = sc;
    g_shift[c] = beta[c] - mu * sc;
}

// ---------------- kernel 9: GEMM2  out = ReLU(BN(rst)) @ W_out + b_out -------
__global__ __launch_bounds__(256) void gemm2_kernel(
    const float* __restrict__ Wout, const float* __restrict__ bout,
    float* __restrict__ out) {
    __shared__ float As[32][129];
    __shared__ float Bs[32][128];
    const int tid = threadIdx.x;
    const int tx = tid & 15, ty = tid >> 4;
    const int row0 = blockIdx.x * 128;

    unsigned long long acc[8][4];
#pragma unroll
    for (int i = 0; i < 8; i++)
#pragma unroll
        for (int p = 0; p < 4; p++) acc[i][p] = 0ULL;

    for (int kt = 0; kt < 512; kt += 32) {
        // A tile with fused BN+ReLU
#pragma unroll
        for (int l = 0; l < 4; l++) {
            int e = (tid + l * 256) * 4;
            int r = e >> 5, k = e & 31;
            float4 val = make_float4(0.f, 0.f, 0.f, 0.f);
            int gr = row0 + r;
            if (gr < N_NODES) {
                float4 x = *(const float4*)(g_rst + gr * HD + kt + k);
                float4 sc = *(const float4*)(g_scale + kt + k);
                float4 sh = *(const float4*)(g_shift + kt + k);
                val.x = fmaxf(sc.x * x.x + sh.x, 0.f);
                val.y = fmaxf(sc.y * x.y + sh.y, 0.f);
                val.z = fmaxf(sc.z * x.z + sh.z, 0.f);
                val.w = fmaxf(sc.w * x.w + sh.w, 0.f);
            }
            As[k + 0][r] = val.x; As[k + 1][r] = val.y;
            As[k + 2][r] = val.z; As[k + 3][r] = val.w;
        }
        // B tile 32x128 from W_out [512 x 128]
#pragma unroll
        for (int l = 0; l < 4; l++) {
            int e = (tid + l * 256) * 4;
            int k = e >> 7, c = e & 127;
            *(float4*)&Bs[k][c] = *(const float4*)(Wout + (kt + k) * 128 + c);
        }
        __syncthreads();
#pragma unroll
        for (int kk = 0; kk < 32; kk++) {
            unsigned long long a2[8], b2[4];
#pragma unroll
            for (int i = 0; i < 8; i++) a2[i] = pack2(As[kk][ty * 8 + i]);
#pragma unroll
            for (int p = 0; p < 4; p++)
                b2[p] = *(const unsigned long long*)&Bs[kk][tx * 8 + p * 2];
#pragma unroll
            for (int i = 0; i < 8; i++)
#pragma unroll
                for (int p = 0; p < 4; p++) fma2(acc[i][p], a2[i], b2[p]);
        }
        __syncthreads();
    }
#pragma unroll
    for (int i = 0; i < 8; i++) {
        int gr = row0 + ty * 8 + i;
        if (gr >= N_NODES) continue;
#pragma unroll
        for (int p = 0; p < 4; p++) {
            float2 v = unpack2(acc[i][p]);
            int gc = tx * 8 + p * 2;
            out[gr * OUTF + gc] = v.x + bout[gc];
            out[gr * OUTF + gc + 1] = v.y + bout[gc + 1];
        }
    }
}

// ---------------- launch ----------------
extern "C" void kernel_launch(void* const* d_in, const int* in_sizes, int n_in,
                              void* d_out, int out_size) {
    const float* feat    = (const float*)d_in[0];
    const int*   src     = (const int*)d_in[1];
    const int*   dst     = (const int*)d_in[2];
    const float* Wfc     = (const float*)d_in[3];
    const float* attn_l  = (const float*)d_in[4];
    const float* attn_r  = (const float*)d_in[5];
    const float* Wres    = (const float*)d_in[6];
    const float* biasg   = (const float*)d_in[7];
    const float* gamma   = (const float*)d_in[8];
    const float* beta    = (const float*)d_in[9];
    const float* Wout    = (const float*)d_in[10];
    const float* bout    = (const float*)d_in[11];
    float* out = (float*)d_out;

    zero_deg_kernel<<<(N_NODES + 255) / 256, 256>>>();
    dim3 g1(8, (N_NODES + 127) / 128);
    gemm1_kernel<<<g1, 256>>>(feat, Wfc, Wres, biasg);
    el_er_kernel<<<(N_NODES * 32 + 255) / 256, 256>>>(attn_l, attn_r);
    hist_kernel<<<(N_EDGES + 255) / 256, 256>>>(dst);
    scan_kernel<<<1, 1024>>>();
    scatter_kernel<<<(N_EDGES + 255) / 256, 256>>>(src, dst);
    agg_kernel<<<(N_NODES * NHEAD * 32 + 255) / 256, 256>>>();
    bn_part_kernel<<<BN_BLOCKS, HD>>>();
    bn_final_kernel<<<1, HD>>>(gamma, beta);
    gemm2_kernel<<<(N_NODES + 127) / 128, 256>>>(Wout, bout, out);
}